// round 14
// baseline (speedup 1.0000x reference)
#include <cuda_runtime.h>
#include <cuda_bf16.h>
#include <math.h>

#define Bz 16
#define Sz 256
#define Cz 17
#define Nz 16
#define Dz 32
#define Ez 4
#define Hz 4
#define DHz 8
#define DFFz 64
#define FULLM 0xffffffffu
#define LOG2E 1.4426950408889634f

// ---------------- scratch (static device memory; no allocations) -------------
__device__ float g_xns[Bz * Sz * Nz];
__device__ int   g_assign[Bz * Sz];
__device__ int   g_lists[Bz * Ez * Sz];
__device__ int   g_counts[Bz * Ez];
__device__ int   g_offs[Bz * Ez];

// LN1 rank-1 factorization artifacts
__device__ float g_PQR[Ez * 3 * 3 * Dz];   // [e][mat q/k/v][basis P/Q/R][d]
__device__ float g_M[Ez * Hz * 9];         // logit bilinear form (scale folded)
__device__ float g_m0[Ez * Hz * 3];        // background logit row (scale folded)
__device__ float g_ABCD[Ez * Hz * 4 * Dz]; // {Pv,Qv,Rv,v0}@Wo per head
__device__ float g_scal[3];                // vW, vb, cv
__device__ float4 g_c4[Bz * Sz * Nz * Hz]; // attention coeffs per (token,n,h)

__device__ __forceinline__ float ex2f(float x) {
    float y;
    asm("ex2.approx.f32 %0, %1;" : "=f"(y) : "f"(x));
    return y;
}

// ---------------- kernel 1: preprocess (blk<256) + route (256) + pre (257) ---
__global__ void front_kernel(const float* __restrict__ x,
                             const float* __restrict__ ox,
                             const float* __restrict__ sW,
                             const float* __restrict__ sb,
                             const float* __restrict__ Wq,
                             const float* __restrict__ Wk,
                             const float* __restrict__ Wv,
                             const float* __restrict__ Wo,
                             const float* __restrict__ ln1_g,
                             const float* __restrict__ ln1_b) {
    int t = threadIdx.x;

    if (blockIdx.x < 256) {
        // ============== preprocess: trend + Fourier season + new_x ==========
        int blk = blockIdx.x;
        int b = blk / Nz;
        int c = blk % Nz;

        __shared__ float xs[Sz];
        __shared__ float ctab[Sz], stab[Sz];
        __shared__ float re_s[129], im_s[129], amp_s[129], amp2_s[129];
        __shared__ float keptre[32], keptim[32];
        __shared__ int   keptf[32];
        __shared__ int   nkept_s;
        __shared__ float thr_s;

        if (t == 0) nkept_s = 0;
        xs[t] = x[(b * Sz + t) * Cz + c];
        float ang = (float)t / 128.0f;
        ctab[t] = cospif(ang);
        stab[t] = sinpif(ang);
        __syncthreads();

        if (t < 129) {
            float re = 0.f, im = 0.f;
            for (int u = 0; u < Sz; u++) {
                int idx = (t * u) & 255;
                float xv = xs[u];
                re += xv * ctab[idx];
                im -= xv * stab[idx];
            }
            re_s[t] = re;
            im_s[t] = im;
            float a = (t == 0) ? -1e38f : sqrtf(re * re + im * im);
            amp_s[t] = a;
            amp2_s[t] = a;
        }
        __syncthreads();

        if (t < 32) {
            float thr = 0.f;
            for (int pass = 0; pass < 4; pass++) {
                unsigned long long best = 0ull;
                #pragma unroll
                for (int cc = 0; cc < 5; cc++) {
                    int f = cc * 32 + t;
                    if (f < 129) {
                        float a = amp2_s[f];
                        if (a > -1e37f) {
                            unsigned long long u =
                                (((unsigned long long)__float_as_uint(a)) << 32) |
                                (unsigned)f;
                            if (u > best) best = u;
                        }
                    }
                }
                #pragma unroll
                for (int off = 16; off > 0; off >>= 1) {
                    unsigned long long o2 = __shfl_xor_sync(FULLM, best, off);
                    if (o2 > best) best = o2;
                }
                int bi = (int)(best & 0xffffffffu);
                thr = __uint_as_float((unsigned)(best >> 32));
                if (t == 0) amp2_s[bi] = -1e38f;
                __syncwarp();
            }
            if (t == 0) thr_s = thr;
        }
        __syncthreads();

        float thr = thr_s;
        if (t < 129 && amp_s[t] >= thr) {
            int p = atomicAdd(&nkept_s, 1);
            if (p < 32) {
                keptf[p] = t;
                keptre[p] = re_s[t];
                keptim[p] = im_s[t];
            }
        }
        __syncthreads();

        float season = 0.f;
        int nk = min(nkept_s, 32);
        for (int j = 0; j < nk; j++) {
            int f = keptf[j];
            float cr = keptre[j], ci = keptim[j];
            int idx = (f * t) & 255;
            if (f == 0)        season += cr;
            else if (f == 128) season += cr * ctab[idx];
            else               season += 2.f * (cr * ctab[idx] - ci * stab[idx]);
        }
        season *= (1.0f / 256.0f);

        float s4 = 0.f, s8 = 0.f, s12 = 0.f;
        #pragma unroll
        for (int i = -1; i <= 2; i++) { int u = min(max(t + i, 0), Sz - 1); s4 += xs[u]; }
        #pragma unroll
        for (int i = -3; i <= 4; i++) { int u = min(max(t + i, 0), Sz - 1); s8 += xs[u]; }
        #pragma unroll
        for (int i = -5; i <= 6; i++) { int u = min(max(t + i, 0), Sz - 1); s12 += xs[u]; }
        float trend = (s4 * 0.25f + s8 * 0.125f + s12 * (1.0f / 12.0f)) * (1.0f / 3.0f);

        g_xns[(b * Sz + t) * Nz + c] = xs[t] + season + trend;

    } else if (blockIdx.x == 256) {
        // ============== routing ==============
        __shared__ float red[256];
        __shared__ float smin_s, smax_s;

        float mn = 3.4e38f, mx = -3.4e38f;
        for (int i = t; i < Bz * Sz; i += 256) {
            float s = ox[i * 2 + 1];
            mn = fminf(mn, s);
            mx = fmaxf(mx, s);
        }
        red[t] = mn; __syncthreads();
        for (int o = 128; o > 0; o >>= 1) {
            if (t < o) red[t] = fminf(red[t], red[t + o]);
            __syncthreads();
        }
        if (t == 0) smin_s = red[0];
        __syncthreads();
        red[t] = mx; __syncthreads();
        for (int o = 128; o > 0; o >>= 1) {
            if (t < o) red[t] = fmaxf(red[t], red[t + o]);
            __syncthreads();
        }
        if (t == 0) smax_s = red[0];
        __syncthreads();

        float bmin = smin_s, bmax = smax_s;
        float step = (bmax - bmin) * 0.25f;
        for (int i = t; i < Bz * Sz; i += 256) {
            float s = ox[i * 2 + 1];
            int cntb = 0;
            #pragma unroll
            for (int k = 0; k < 5; k++) {
                float bv = bmin + step * (float)k;
                if (bv <= s) cntb++;
            }
            int a = cntb - 1;
            a = max(0, min(Ez - 1, a));
            g_assign[i] = a;
        }
        __syncthreads();

        int warp = t >> 5, lane = t & 31;
        for (int pe = warp; pe < Bz * Ez; pe += 8) {
            int b = pe / Ez, e = pe % Ez;
            int cnt = 0;
            for (int s0 = 0; s0 < Sz; s0 += 32) {
                int s = s0 + lane;
                int a = g_assign[b * Sz + s];
                unsigned bal = __ballot_sync(FULLM, a == e);
                int pos = cnt + __popc(bal & ((1u << lane) - 1u));
                if (a == e) g_lists[pe * Sz + pos] = s;
                cnt += __popc(bal);
            }
            if (lane == 0) g_counts[pe] = cnt;
        }
        __syncthreads();

        if (t < Bz) {
            int off = 0;
            #pragma unroll
            for (int e = 0; e < Ez; e++) {
                g_offs[t * Ez + e] = off;
                off += g_counts[t * Ez + e];
            }
        }
    } else {
        // ============== rank-1 LN factorization precompute ==============
        __shared__ float uWs[Dz], ubs[Dz];
        __shared__ float vbs_sh;

        if (t == 0) {
            float mW = 0.f, mb = 0.f;
            for (int i = 0; i < Dz; i++) { mW += sW[i]; mb += sb[i]; }
            mW *= (1.0f / Dz); mb *= (1.0f / Dz);
            float vW = 0.f, vb = 0.f, cv = 0.f;
            for (int i = 0; i < Dz; i++) {
                float uw = sW[i] - mW, ub = sb[i] - mb;
                uWs[i] = uw; ubs[i] = ub;
                vW += uw * uw; vb += ub * ub; cv += uw * ub;
            }
            vW *= (1.0f / Dz); vb *= (1.0f / Dz); cv *= (1.0f / Dz);
            g_scal[0] = vW; g_scal[1] = vb; g_scal[2] = cv;
            vbs_sh = vb;
        }
        __syncthreads();

        if (t < Ez * Dz) {
            int e = t >> 5, d = t & 31;
            #pragma unroll
            for (int m = 0; m < 3; m++) {
                const float* W = ((m == 0) ? Wq : (m == 1) ? Wk : Wv) + e * Dz * Dz;
                float P = 0.f, Q = 0.f, R = 0.f;
                for (int i = 0; i < Dz; i++) {
                    float w = W[i * Dz + d];
                    float g = ln1_g[e * Dz + i];
                    P += uWs[i] * g * w;
                    Q += ubs[i] * g * w;
                    R += ln1_b[e * Dz + i] * w;
                }
                g_PQR[((e * 3 + m) * 3 + 0) * Dz + d] = P;
                g_PQR[((e * 3 + m) * 3 + 1) * Dz + d] = Q;
                g_PQR[((e * 3 + m) * 3 + 2) * Dz + d] = R;
            }
        }
        __syncthreads();

        const float scale = 0.35355339059327373f;   // 1/sqrt(8)
        float a0 = rsqrtf(vbs_sh + 1e-5f);          // alpha at a=0 (background)

        if (t < Ez * Hz) {
            int e = t >> 2, h = t & 3;
            #pragma unroll
            for (int r = 0; r < 3; r++) {
                const float* qb = &g_PQR[((e * 3 + 0) * 3 + r) * Dz + h * 8];
                #pragma unroll
                for (int c = 0; c < 3; c++) {
                    const float* kb = &g_PQR[((e * 3 + 1) * 3 + c) * Dz + h * 8];
                    float s = 0.f;
                    #pragma unroll
                    for (int d = 0; d < 8; d++) s += qb[d] * kb[d];
                    g_M[(e * Hz + h) * 9 + r * 3 + c] = s * scale;
                }
                const float* Qk = &g_PQR[((e * 3 + 1) * 3 + 1) * Dz + h * 8];
                const float* Rk = &g_PQR[((e * 3 + 1) * 3 + 2) * Dz + h * 8];
                float s0 = 0.f;
                #pragma unroll
                for (int d = 0; d < 8; d++) s0 += qb[d] * (a0 * Qk[d] + Rk[d]);
                g_m0[(e * Hz + h) * 3 + r] = s0 * scale;
            }
        }

        if (t < Ez * Dz) {
            int e = t >> 5, d = t & 31;
            const float* Pv = &g_PQR[((e * 3 + 2) * 3 + 0) * Dz];
            const float* Qv = &g_PQR[((e * 3 + 2) * 3 + 1) * Dz];
            const float* Rv = &g_PQR[((e * 3 + 2) * 3 + 2) * Dz];
            const float* WoE = Wo + e * Dz * Dz;
            #pragma unroll
            for (int h = 0; h < Hz; h++) {
                float A = 0.f, B = 0.f, C = 0.f, Dv = 0.f;
                #pragma unroll
                for (int i = 0; i < 8; i++) {
                    int ii = h * 8 + i;
                    float w = WoE[ii * Dz + d];
                    A += Pv[ii] * w;
                    B += Qv[ii] * w;
                    C += Rv[ii] * w;
                    Dv += (a0 * Qv[ii] + Rv[ii]) * w;
                }
                g_ABCD[((e * Hz + h) * 4 + 0) * Dz + d] = A;
                g_ABCD[((e * Hz + h) * 4 + 1) * Dz + d] = B;
                g_ABCD[((e * Hz + h) * 4 + 2) * Dz + d] = C;
                g_ABCD[((e * Hz + h) * 4 + 3) * Dz + d] = Dv;
            }
        }
    }
}

// ---------------- kernel 2: attention via 3x3 bilinear logits ----------------
// grid = pe*Nz = 1024; block 256 (64 queries x 4 head-lanes); log2e folded,
// raw ex2.approx for exp.
__global__ __launch_bounds__(256) void attn_kernel() {
    int blk = blockIdx.x;
    int n = blk & 15;
    int pe = blk >> 4;
    int b = pe / Ez, e = pe % Ez;
    int cnt = g_counts[pe];
    if (cnt == 0) return;
    int off = g_offs[pe];
    long gbase = (long)b * Sz + off;

    __shared__ int lst_s[Sz];
    __shared__ float4 yk[Sz * Hz];     // 16KB: y = (log2e*M_h) @ uk per (key,h)
    __shared__ float2 uks[Sz];         // 2KB
    __shared__ float M_s[Hz * 9];
    __shared__ float m0_s[Hz * 3];

    int t = threadIdx.x;
    if (t < Hz * 9)  M_s[t]  = g_M[e * Hz * 9 + t] * LOG2E;
    if (t < Hz * 3)  m0_s[t] = g_m0[e * Hz * 3 + t] * LOG2E;
    for (int i = t; i < cnt; i += 256) lst_s[i] = g_lists[pe * Sz + i];
    __syncthreads();

    // per-key scalars (alpha*a, alpha)
    float vW = g_scal[0], vb = g_scal[1], cv = g_scal[2];
    for (int i = t; i < cnt; i += 256) {
        float a = g_xns[(b * Sz + lst_s[i]) * Nz + n];
        float al = rsqrtf((a * vW + 2.f * cv) * a + vb + 1e-5f);
        uks[i] = make_float2(al * a, al);
    }
    __syncthreads();

    for (int i = t; i < cnt * Hz; i += 256) {
        int j = i >> 2, h = i & 3;
        float2 u = uks[j];
        const float* M = &M_s[h * 9];
        float y0 = M[0] * u.x + M[1] * u.y + M[2];
        float y1 = M[3] * u.x + M[4] * u.y + M[5];
        float y2 = M[6] * u.x + M[7] * u.y + M[8];
        yk[j * Hz + h] = make_float4(y0, y1, y2, 0.f);
    }
    __syncthreads();

    int lq = t >> 2, hh = t & 3;
    float fnbg = (float)(Sz - cnt);
    int npass = (cnt + 63) >> 6;

    for (int p = 0; p < npass; p++) {
        int qi = p * 64 + lq;
        bool active = qi < cnt;
        int qc = active ? qi : cnt - 1;

        float2 uq = uks[qc];
        const float* m0 = &m0_s[hh * 3];
        float l0 = m0[0] * uq.x + m0[1] * uq.y + m0[2];

        float T0 = 0.f, T1 = 0.f, T2 = 0.f;
        #pragma unroll 4
        for (int j = 0; j < cnt; j++) {
            float4 y = yk[j * Hz + hh];
            float l = uq.x * y.x + uq.y * y.y + y.z;
            float w = ex2f(l - l0);
            float2 uk = uks[j];
            T0 += w * uk.x;
            T1 += w * uk.y;
            T2 += w;
        }
        float inv = 1.0f / (T2 + fnbg);
        if (active) {
            g_c4[((gbase + qi) * Nz + n) * Hz + hh] =
                make_float4(T0 * inv, T1 * inv, T2 * inv, fnbg * inv);
        }
    }
}

// ---------------- kernel 3: fused tail (Wo+LN2+FFN, no global round trips) ---
// grid = (b,e)*16 tiles; 128 thr (4 warps x 4 channels); lane = dim / 2 f-cols
// abcd + W1 register-resident; W2 streamed via __ldg (L1-resident).
__global__ __launch_bounds__(128, 4) void tail_kernel(
        const float* __restrict__ sW,  const float* __restrict__ sb,
        const float* __restrict__ ln2_g, const float* __restrict__ ln2_b,
        const float* __restrict__ b2,
        const float* __restrict__ W1, const float* __restrict__ b1,
        const float* __restrict__ W2, float* __restrict__ out) {
    int blk = blockIdx.x;
    int pe = blk >> 4, tile = blk & 15;
    int b = pe / Ez, e = pe % Ez;
    int cnt = g_counts[pe];
    if (cnt == 0) return;
    int off = g_offs[pe];
    int t = threadIdx.x, warp = t >> 5, lane = t & 31;

    __shared__ float z2_s[4][4][Dz];
    __shared__ float f_s[4][4][DFFz];

    float abcd[16];
    #pragma unroll
    for (int h = 0; h < Hz; h++)
        #pragma unroll
        for (int r = 0; r < 4; r++)
            abcd[h * 4 + r] = __ldg(&g_ABCD[((e * Hz + h) * 4 + r) * Dz + lane]);

    float w1a[Dz], w1b[Dz];
    #pragma unroll
    for (int i = 0; i < Dz; i++) {
        w1a[i] = __ldg(&W1[e * Dz * DFFz + i * DFFz + lane]);
        w1b[i] = __ldg(&W1[e * Dz * DFFz + i * DFFz + 32 + lane]);
    }

    const float sWl  = __ldg(&sW[lane]);
    const float sbl  = __ldg(&sb[lane]);
    const float g2l  = __ldg(&ln2_g[e * Dz + lane]);
    const float bl2l = __ldg(&ln2_b[e * Dz + lane]);
    const float b2l  = __ldg(&b2[e * Dz + lane]);
    const float b1a  = __ldg(&b1[e * DFFz + lane]);
    const float b1b  = __ldg(&b1[e * DFFz + 32 + lane]);
    const float* W2e = W2 + e * DFFz * Dz;

    const int* lst = &g_lists[pe * Sz];
    int n0 = warp * 4;

    for (int ti = tile; ti < cnt; ti += 16) {
        int s = lst[ti];
        long gpos = (long)b * Sz + off + ti;

        // ---- Wo (via ABCD coeffs) + LN2 ----
        float h1c[4];
        #pragma unroll
        for (int ch = 0; ch < 4; ch++) {
            int n = n0 + ch;
            float a = __ldg(&g_xns[((long)b * Sz + s) * Nz + n]);
            float h1 = a * sWl + sbl;
            const float4* cp = &g_c4[(gpos * Nz + n) * Hz];
            #pragma unroll
            for (int h = 0; h < Hz; h++) {
                float4 c = __ldg(cp + h);       // broadcast across lanes
                h1 += c.x * abcd[h * 4 + 0] + c.y * abcd[h * 4 + 1]
                    + c.z * abcd[h * 4 + 2] + c.w * abcd[h * 4 + 3];
            }
            float mu = h1;
            #pragma unroll
            for (int o2 = 16; o2 > 0; o2 >>= 1)
                mu += __shfl_xor_sync(FULLM, mu, o2);
            mu *= (1.0f / Dz);
            float df = h1 - mu;
            float var = df * df;
            #pragma unroll
            for (int o2 = 16; o2 > 0; o2 >>= 1)
                var += __shfl_xor_sync(FULLM, var, o2);
            var *= (1.0f / Dz);
            float z = df * rsqrtf(var + 1e-5f) * g2l + bl2l;
            z2_s[warp][ch][lane] = z;
            h1c[ch] = h1 + b2l;
        }
        __syncwarp();

        // ---- FFN layer 1: f = relu(z2 @ W1 + b1) ----
        #pragma unroll
        for (int ch = 0; ch < 4; ch++) {
            float f0 = b1a, f1 = b1b;
            const float4* zp = (const float4*)z2_s[warp][ch];
            #pragma unroll
            for (int i4 = 0; i4 < 8; i4++) {
                float4 z = zp[i4];
                f0 += z.x * w1a[i4*4+0] + z.y * w1a[i4*4+1]
                    + z.z * w1a[i4*4+2] + z.w * w1a[i4*4+3];
                f1 += z.x * w1b[i4*4+0] + z.y * w1b[i4*4+1]
                    + z.z * w1b[i4*4+2] + z.w * w1b[i4*4+3];
            }
            f_s[warp][ch][lane]      = fmaxf(f0, 0.f);
            f_s[warp][ch][32 + lane] = fmaxf(f1, 0.f);
        }
        __syncwarp();

        // ---- FFN layer 2: out = h1 + f @ W2 (W2 streamed, L1-hot) ----
        #pragma unroll
        for (int ch = 0; ch < 4; ch++) {
            float acc = h1c[ch];
            const float* fp = f_s[warp][ch];
            #pragma unroll 16
            for (int j = 0; j < DFFz; j++)
                acc += fp[j] * __ldg(&W2e[j * Dz + lane]);
            out[(((long)b * Sz + s) * Nz + n0 + ch) * Dz + lane] = acc;
        }
        __syncwarp();
    }
}

// ---------------- launch ------------------------------------------------------
extern "C" void kernel_launch(void* const* d_in, const int* in_sizes, int n_in,
                              void* d_out, int out_size) {
    const float* x        = (const float*)d_in[0];
    const float* ox       = (const float*)d_in[1];
    const float* start_W  = (const float*)d_in[2];
    const float* start_b  = (const float*)d_in[3];
    const float* Wq       = (const float*)d_in[4];
    const float* Wk       = (const float*)d_in[5];
    const float* Wv       = (const float*)d_in[6];
    const float* Wo       = (const float*)d_in[7];
    const float* ln1_g    = (const float*)d_in[8];
    const float* ln1_b    = (const float*)d_in[9];
    const float* ln2_g    = (const float*)d_in[10];
    const float* ln2_b    = (const float*)d_in[11];
    const float* W1       = (const float*)d_in[12];
    const float* b1       = (const float*)d_in[13];
    const float* W2       = (const float*)d_in[14];
    const float* b2       = (const float*)d_in[15];
    float* out = (float*)d_out;

    front_kernel<<<258, 256>>>(x, ox, start_W, start_b, Wq, Wk, Wv, Wo,
                               ln1_g, ln1_b);
    attn_kernel<<<Bz * Ez * Nz, 256>>>();
    tail_kernel<<<Bz * Ez * 16, 128>>>(start_W, start_b, ln2_g, ln2_b, b2,
                                       W1, b1, W2, out);
}

// round 15
// speedup vs baseline: 1.1574x; 1.1574x over previous
#include <cuda_runtime.h>
#include <cuda_bf16.h>
#include <math.h>

#define Bz 16
#define Sz 256
#define Cz 17
#define Nz 16
#define Dz 32
#define Ez 4
#define Hz 4
#define DHz 8
#define DFFz 64
#define FULLM 0xffffffffu
#define LOG2E 1.4426950408889634f

// ---------------- scratch (static device memory; no allocations) -------------
__device__ float g_xns[Bz * Sz * Nz];
__device__ int   g_assign[Bz * Sz];
__device__ int   g_lists[Bz * Ez * Sz];
__device__ int   g_counts[Bz * Ez];
__device__ int   g_offs[Bz * Ez];

// LN1 rank-1 factorization artifacts
__device__ float g_PQR[Ez * 3 * 3 * Dz];   // [e][mat q/k/v][basis P/Q/R][d]
__device__ float g_M[Ez * Hz * 9];         // logit bilinear form (scale folded)
__device__ float g_m0[Ez * Hz * 3];        // background logit row (scale folded)
__device__ float g_ABCD[Ez * Hz * 4 * Dz]; // {Pv,Qv,Rv,v0}@Wo per head
__device__ float g_scal[3];                // vW, vb, cv
__device__ float4 g_c4[Bz * Sz * Nz * Hz]; // attention coeffs per (token,n,h)

__device__ float g_z2[Bz * Sz * Nz * Dz];
__device__ float g_h1[Bz * Sz * Nz * Dz];

__device__ __forceinline__ float ex2f(float x) {
    float y;
    asm("ex2.approx.f32 %0, %1;" : "=f"(y) : "f"(x));
    return y;
}

// ---------------- kernel 1: preprocess (blk<256) + route (256) + pre (257) ---
__global__ void front_kernel(const float* __restrict__ x,
                             const float* __restrict__ ox,
                             const float* __restrict__ sW,
                             const float* __restrict__ sb,
                             const float* __restrict__ Wq,
                             const float* __restrict__ Wk,
                             const float* __restrict__ Wv,
                             const float* __restrict__ Wo,
                             const float* __restrict__ ln1_g,
                             const float* __restrict__ ln1_b) {
    int t = threadIdx.x;

    if (blockIdx.x < 256) {
        // ============== preprocess: trend + Fourier season + new_x ==========
        int blk = blockIdx.x;
        int b = blk / Nz;
        int c = blk % Nz;

        __shared__ float xs[Sz];
        __shared__ float ctab[Sz], stab[Sz];
        __shared__ float re_s[129], im_s[129], amp_s[129], amp2_s[129];
        __shared__ float keptre[32], keptim[32];
        __shared__ int   keptf[32];
        __shared__ int   nkept_s;
        __shared__ float thr_s;

        if (t == 0) nkept_s = 0;
        xs[t] = x[(b * Sz + t) * Cz + c];
        float ang = (float)t / 128.0f;
        ctab[t] = cospif(ang);
        stab[t] = sinpif(ang);
        __syncthreads();

        // DFT: 2 threads per frequency (even/odd u halves), strength-reduced
        // twiddle index; pair-combined via shfl. f=128 handled by warp 0.
        {
            int f2 = t >> 1, half = t & 1;
            float re = 0.f, im = 0.f;
            int idx = (f2 * half) & 255;
            int step = (2 * f2) & 255;
            for (int u = half; u < Sz; u += 2) {
                float xv = xs[u];
                re += xv * ctab[idx];
                im -= xv * stab[idx];
                idx = (idx + step) & 255;
            }
            re += __shfl_xor_sync(FULLM, re, 1);
            im += __shfl_xor_sync(FULLM, im, 1);
            if (half == 0) {
                re_s[f2] = re;
                im_s[f2] = im;
                float a = (f2 == 0) ? -1e38f : sqrtf(re * re + im * im);
                amp_s[f2] = a;
                amp2_s[f2] = a;
            }
            if (t < 32) {   // f = 128: sum x[u]*(-1)^u
                float acc = 0.f;
                #pragma unroll
                for (int u = t; u < Sz; u += 32) {
                    float xv = xs[u];
                    acc += (u & 1) ? -xv : xv;
                }
                #pragma unroll
                for (int o2 = 16; o2 > 0; o2 >>= 1)
                    acc += __shfl_xor_sync(FULLM, acc, o2);
                if (t == 0) {
                    re_s[128] = acc;
                    im_s[128] = 0.f;
                    float a = fabsf(acc);
                    amp_s[128] = a;
                    amp2_s[128] = a;
                }
            }
        }
        __syncthreads();

        if (t < 32) {
            float thr = 0.f;
            for (int pass = 0; pass < 4; pass++) {
                unsigned long long best = 0ull;
                #pragma unroll
                for (int cc = 0; cc < 5; cc++) {
                    int f = cc * 32 + t;
                    if (f < 129) {
                        float a = amp2_s[f];
                        if (a > -1e37f) {
                            unsigned long long u =
                                (((unsigned long long)__float_as_uint(a)) << 32) |
                                (unsigned)f;
                            if (u > best) best = u;
                        }
                    }
                }
                #pragma unroll
                for (int off = 16; off > 0; off >>= 1) {
                    unsigned long long o2 = __shfl_xor_sync(FULLM, best, off);
                    if (o2 > best) best = o2;
                }
                int bi = (int)(best & 0xffffffffu);
                thr = __uint_as_float((unsigned)(best >> 32));
                if (t == 0) amp2_s[bi] = -1e38f;
                __syncwarp();
            }
            if (t == 0) thr_s = thr;
        }
        __syncthreads();

        float thr = thr_s;
        if (t < 129 && amp_s[t] >= thr) {
            int p = atomicAdd(&nkept_s, 1);
            if (p < 32) {
                keptf[p] = t;
                keptre[p] = re_s[t];
                keptim[p] = im_s[t];
            }
        }
        __syncthreads();

        float season = 0.f;
        int nk = min(nkept_s, 32);
        for (int j = 0; j < nk; j++) {
            int f = keptf[j];
            float cr = keptre[j], ci = keptim[j];
            int idx = (f * t) & 255;
            if (f == 0)        season += cr;
            else if (f == 128) season += cr * ctab[idx];
            else               season += 2.f * (cr * ctab[idx] - ci * stab[idx]);
        }
        season *= (1.0f / 256.0f);

        float s4 = 0.f, s8 = 0.f, s12 = 0.f;
        #pragma unroll
        for (int i = -1; i <= 2; i++) { int u = min(max(t + i, 0), Sz - 1); s4 += xs[u]; }
        #pragma unroll
        for (int i = -3; i <= 4; i++) { int u = min(max(t + i, 0), Sz - 1); s8 += xs[u]; }
        #pragma unroll
        for (int i = -5; i <= 6; i++) { int u = min(max(t + i, 0), Sz - 1); s12 += xs[u]; }
        float trend = (s4 * 0.25f + s8 * 0.125f + s12 * (1.0f / 12.0f)) * (1.0f / 3.0f);

        g_xns[(b * Sz + t) * Nz + c] = xs[t] + season + trend;

    } else if (blockIdx.x == 256) {
        // ============== routing ==============
        __shared__ float red[256];
        __shared__ float smin_s, smax_s;

        float mn = 3.4e38f, mx = -3.4e38f;
        for (int i = t; i < Bz * Sz; i += 256) {
            float s = ox[i * 2 + 1];
            mn = fminf(mn, s);
            mx = fmaxf(mx, s);
        }
        red[t] = mn; __syncthreads();
        for (int o = 128; o > 0; o >>= 1) {
            if (t < o) red[t] = fminf(red[t], red[t + o]);
            __syncthreads();
        }
        if (t == 0) smin_s = red[0];
        __syncthreads();
        red[t] = mx; __syncthreads();
        for (int o = 128; o > 0; o >>= 1) {
            if (t < o) red[t] = fmaxf(red[t], red[t + o]);
            __syncthreads();
        }
        if (t == 0) smax_s = red[0];
        __syncthreads();

        float bmin = smin_s, bmax = smax_s;
        float step = (bmax - bmin) * 0.25f;
        for (int i = t; i < Bz * Sz; i += 256) {
            float s = ox[i * 2 + 1];
            int cntb = 0;
            #pragma unroll
            for (int k = 0; k < 5; k++) {
                float bv = bmin + step * (float)k;
                if (bv <= s) cntb++;
            }
            int a = cntb - 1;
            a = max(0, min(Ez - 1, a));
            g_assign[i] = a;
        }
        __syncthreads();

        int warp = t >> 5, lane = t & 31;
        for (int pe = warp; pe < Bz * Ez; pe += 8) {
            int b = pe / Ez, e = pe % Ez;
            int cnt = 0;
            for (int s0 = 0; s0 < Sz; s0 += 32) {
                int s = s0 + lane;
                int a = g_assign[b * Sz + s];
                unsigned bal = __ballot_sync(FULLM, a == e);
                int pos = cnt + __popc(bal & ((1u << lane) - 1u));
                if (a == e) g_lists[pe * Sz + pos] = s;
                cnt += __popc(bal);
            }
            if (lane == 0) g_counts[pe] = cnt;
        }
        __syncthreads();

        if (t < Bz) {
            int off = 0;
            #pragma unroll
            for (int e = 0; e < Ez; e++) {
                g_offs[t * Ez + e] = off;
                off += g_counts[t * Ez + e];
            }
        }
    } else {
        // ============== rank-1 LN factorization precompute ==============
        __shared__ float uWs[Dz], ubs[Dz];
        __shared__ float vbs_sh;

        if (t == 0) {
            float mW = 0.f, mb = 0.f;
            for (int i = 0; i < Dz; i++) { mW += sW[i]; mb += sb[i]; }
            mW *= (1.0f / Dz); mb *= (1.0f / Dz);
            float vW = 0.f, vb = 0.f, cv = 0.f;
            for (int i = 0; i < Dz; i++) {
                float uw = sW[i] - mW, ub = sb[i] - mb;
                uWs[i] = uw; ubs[i] = ub;
                vW += uw * uw; vb += ub * ub; cv += uw * ub;
            }
            vW *= (1.0f / Dz); vb *= (1.0f / Dz); cv *= (1.0f / Dz);
            g_scal[0] = vW; g_scal[1] = vb; g_scal[2] = cv;
            vbs_sh = vb;
        }
        __syncthreads();

        if (t < Ez * Dz) {
            int e = t >> 5, d = t & 31;
            #pragma unroll
            for (int m = 0; m < 3; m++) {
                const float* W = ((m == 0) ? Wq : (m == 1) ? Wk : Wv) + e * Dz * Dz;
                float P = 0.f, Q = 0.f, R = 0.f;
                for (int i = 0; i < Dz; i++) {
                    float w = W[i * Dz + d];
                    float g = ln1_g[e * Dz + i];
                    P += uWs[i] * g * w;
                    Q += ubs[i] * g * w;
                    R += ln1_b[e * Dz + i] * w;
                }
                g_PQR[((e * 3 + m) * 3 + 0) * Dz + d] = P;
                g_PQR[((e * 3 + m) * 3 + 1) * Dz + d] = Q;
                g_PQR[((e * 3 + m) * 3 + 2) * Dz + d] = R;
            }
        }
        __syncthreads();

        const float scale = 0.35355339059327373f;   // 1/sqrt(8)
        float a0 = rsqrtf(vbs_sh + 1e-5f);          // alpha at a=0 (background)

        if (t < Ez * Hz) {
            int e = t >> 2, h = t & 3;
            #pragma unroll
            for (int r = 0; r < 3; r++) {
                const float* qb = &g_PQR[((e * 3 + 0) * 3 + r) * Dz + h * 8];
                #pragma unroll
                for (int c = 0; c < 3; c++) {
                    const float* kb = &g_PQR[((e * 3 + 1) * 3 + c) * Dz + h * 8];
                    float s = 0.f;
                    #pragma unroll
                    for (int d = 0; d < 8; d++) s += qb[d] * kb[d];
                    g_M[(e * Hz + h) * 9 + r * 3 + c] = s * scale;
                }
                const float* Qk = &g_PQR[((e * 3 + 1) * 3 + 1) * Dz + h * 8];
                const float* Rk = &g_PQR[((e * 3 + 1) * 3 + 2) * Dz + h * 8];
                float s0 = 0.f;
                #pragma unroll
                for (int d = 0; d < 8; d++) s0 += qb[d] * (a0 * Qk[d] + Rk[d]);
                g_m0[(e * Hz + h) * 3 + r] = s0 * scale;
            }
        }

        if (t < Ez * Dz) {
            int e = t >> 5, d = t & 31;
            const float* Pv = &g_PQR[((e * 3 + 2) * 3 + 0) * Dz];
            const float* Qv = &g_PQR[((e * 3 + 2) * 3 + 1) * Dz];
            const float* Rv = &g_PQR[((e * 3 + 2) * 3 + 2) * Dz];
            const float* WoE = Wo + e * Dz * Dz;
            #pragma unroll
            for (int h = 0; h < Hz; h++) {
                float A = 0.f, B = 0.f, C = 0.f, Dv = 0.f;
                #pragma unroll
                for (int i = 0; i < 8; i++) {
                    int ii = h * 8 + i;
                    float w = WoE[ii * Dz + d];
                    A += Pv[ii] * w;
                    B += Qv[ii] * w;
                    C += Rv[ii] * w;
                    Dv += (a0 * Qv[ii] + Rv[ii]) * w;
                }
                g_ABCD[((e * Hz + h) * 4 + 0) * Dz + d] = A;
                g_ABCD[((e * Hz + h) * 4 + 1) * Dz + d] = B;
                g_ABCD[((e * Hz + h) * 4 + 2) * Dz + d] = C;
                g_ABCD[((e * Hz + h) * 4 + 3) * Dz + d] = Dv;
            }
        }
    }
}

// ---------------- kernel 2: attention via 3x3 bilinear logits ----------------
// grid = pe*Nz = 1024; block 256 (64 queries x 4 head-lanes); log2e folded,
// raw ex2.approx for exp.
__global__ __launch_bounds__(256) void attn_kernel() {
    int blk = blockIdx.x;
    int n = blk & 15;
    int pe = blk >> 4;
    int b = pe / Ez, e = pe % Ez;
    int cnt = g_counts[pe];
    if (cnt == 0) return;
    int off = g_offs[pe];
    long gbase = (long)b * Sz + off;

    __shared__ int lst_s[Sz];
    __shared__ float4 yk[Sz * Hz];     // 16KB
    __shared__ float2 uks[Sz];         // 2KB
    __shared__ float M_s[Hz * 9];
    __shared__ float m0_s[Hz * 3];

    int t = threadIdx.x;
    if (t < Hz * 9)  M_s[t]  = g_M[e * Hz * 9 + t] * LOG2E;
    if (t < Hz * 3)  m0_s[t] = g_m0[e * Hz * 3 + t] * LOG2E;
    for (int i = t; i < cnt; i += 256) lst_s[i] = g_lists[pe * Sz + i];
    __syncthreads();

    float vW = g_scal[0], vb = g_scal[1], cv = g_scal[2];
    for (int i = t; i < cnt; i += 256) {
        float a = g_xns[(b * Sz + lst_s[i]) * Nz + n];
        float al = rsqrtf((a * vW + 2.f * cv) * a + vb + 1e-5f);
        uks[i] = make_float2(al * a, al);
    }
    __syncthreads();

    for (int i = t; i < cnt * Hz; i += 256) {
        int j = i >> 2, h = i & 3;
        float2 u = uks[j];
        const float* M = &M_s[h * 9];
        float y0 = M[0] * u.x + M[1] * u.y + M[2];
        float y1 = M[3] * u.x + M[4] * u.y + M[5];
        float y2 = M[6] * u.x + M[7] * u.y + M[8];
        yk[j * Hz + h] = make_float4(y0, y1, y2, 0.f);
    }
    __syncthreads();

    int lq = t >> 2, hh = t & 3;
    float fnbg = (float)(Sz - cnt);
    int npass = (cnt + 63) >> 6;

    for (int p = 0; p < npass; p++) {
        int qi = p * 64 + lq;
        bool active = qi < cnt;
        int qc = active ? qi : cnt - 1;

        float2 uq = uks[qc];
        const float* m0 = &m0_s[hh * 3];
        float l0 = m0[0] * uq.x + m0[1] * uq.y + m0[2];

        float T0 = 0.f, T1 = 0.f, T2 = 0.f;
        #pragma unroll 4
        for (int j = 0; j < cnt; j++) {
            float4 y = yk[j * Hz + hh];
            float l = uq.x * y.x + uq.y * y.y + y.z;
            float w = ex2f(l - l0);
            float2 uk = uks[j];
            T0 += w * uk.x;
            T1 += w * uk.y;
            T2 += w;
        }
        float inv = 1.0f / (T2 + fnbg);
        if (active) {
            g_c4[((gbase + qi) * Nz + n) * Hz + hh] =
                make_float4(T0 * inv, T1 * inv, T2 * inv, fnbg * inv);
        }
    }
}

// ---------------- kernel 3: h1 from coeffs + LN2 -> z2, h1(+b2) --------------
// grid = (b,e)*16 tiles; 128 thr (4 warps x 4 channels); lane = dim
__global__ __launch_bounds__(128, 6) void tail1_kernel(
        const float* __restrict__ sW,  const float* __restrict__ sb,
        const float* __restrict__ ln2_g, const float* __restrict__ ln2_b,
        const float* __restrict__ b2) {
    int blk = blockIdx.x;
    int pe = blk >> 4, tile = blk & 15;
    int b = pe / Ez, e = pe % Ez;
    int cnt = g_counts[pe];
    if (cnt == 0) return;
    int off = g_offs[pe];
    int t = threadIdx.x, warp = t >> 5, lane = t & 31;

    float abcd[16];
    #pragma unroll
    for (int h = 0; h < Hz; h++)
        #pragma unroll
        for (int r = 0; r < 4; r++)
            abcd[h * 4 + r] = __ldg(&g_ABCD[((e * Hz + h) * 4 + r) * Dz + lane]);

    const float sWl  = __ldg(&sW[lane]);
    const float sbl  = __ldg(&sb[lane]);
    const float g2l  = __ldg(&ln2_g[e * Dz + lane]);
    const float bl2l = __ldg(&ln2_b[e * Dz + lane]);
    const float b2l  = __ldg(&b2[e * Dz + lane]);

    const int* lst = &g_lists[pe * Sz];
    int n0 = warp * 4;

    for (int ti = tile; ti < cnt; ti += 16) {
        int s = lst[ti];
        long gpos = (long)b * Sz + off + ti;

        #pragma unroll
        for (int ch = 0; ch < 4; ch++) {
            int n = n0 + ch;
            float a = __ldg(&g_xns[((long)b * Sz + s) * Nz + n]);
            float h1 = a * sWl + sbl;
            const float4* cp = &g_c4[(gpos * Nz + n) * Hz];
            #pragma unroll
            for (int h = 0; h < Hz; h++) {
                float4 c = __ldg(cp + h);       // broadcast across lanes
                h1 += c.x * abcd[h * 4 + 0] + c.y * abcd[h * 4 + 1]
                    + c.z * abcd[h * 4 + 2] + c.w * abcd[h * 4 + 3];
            }
            float mu = h1;
            #pragma unroll
            for (int o2 = 16; o2 > 0; o2 >>= 1)
                mu += __shfl_xor_sync(FULLM, mu, o2);
            mu *= (1.0f / Dz);
            float df = h1 - mu;
            float var = df * df;
            #pragma unroll
            for (int o2 = 16; o2 > 0; o2 >>= 1)
                var += __shfl_xor_sync(FULLM, var, o2);
            var *= (1.0f / Dz);
            float z = df * rsqrtf(var + 1e-5f) * g2l + bl2l;
            g_z2[(gpos * Nz + n) * Dz + lane] = z;
            g_h1[(gpos * Nz + n) * Dz + lane] = h1 + b2l;
        }
    }
}

// ---------------- kernel 4: fused FFN (f in smem, W1/W2 in registers) --------
// grid = (b,e)*16 tiles; 128 thr (4 warps x 4 channels); lane = dim / 2 f-cols
__global__ __launch_bounds__(128, 3) void tail23_kernel(
        const float* __restrict__ W1, const float* __restrict__ b1,
        const float* __restrict__ W2, float* __restrict__ out) {
    int blk = blockIdx.x;
    int pe = blk >> 4, tile = blk & 15;
    int b = pe / Ez, e = pe % Ez;
    int cnt = g_counts[pe];
    if (cnt == 0) return;
    int off = g_offs[pe];
    int t = threadIdx.x, warp = t >> 5, lane = t & 31;

    __shared__ float z2_s[4][4][Dz];
    __shared__ float f_s[4][4][DFFz];

    float w1a[Dz], w1b[Dz], w2[DFFz];
    #pragma unroll
    for (int i = 0; i < Dz; i++) {
        w1a[i] = __ldg(&W1[e * Dz * DFFz + i * DFFz + lane]);
        w1b[i] = __ldg(&W1[e * Dz * DFFz + i * DFFz + 32 + lane]);
    }
    #pragma unroll
    for (int j = 0; j < DFFz; j++)
        w2[j] = __ldg(&W2[e * DFFz * Dz + j * Dz + lane]);

    const float b1a = __ldg(&b1[e * DFFz + lane]);
    const float b1b = __ldg(&b1[e * DFFz + 32 + lane]);

    const int* lst = &g_lists[pe * Sz];
    int n0 = warp * 4;

    for (int ti = tile; ti < cnt; ti += 16) {
        int s = lst[ti];
        long gpos = (long)b * Sz + off + ti;

        #pragma unroll
        for (int ch = 0; ch < 4; ch++)
            z2_s[warp][ch][lane] = g_z2[(gpos * Nz + n0 + ch) * Dz + lane];
        __syncwarp();

        // FFN layer 1: f = relu(z2 @ W1 + b1)
        #pragma unroll
        for (int ch = 0; ch < 4; ch++) {
            float f0 = b1a, f1 = b1b;
            const float4* zp = (const float4*)z2_s[warp][ch];
            #pragma unroll
            for (int i4 = 0; i4 < 8; i4++) {
                float4 z = zp[i4];
                f0 += z.x * w1a[i4*4+0] + z.y * w1a[i4*4+1]
                    + z.z * w1a[i4*4+2] + z.w * w1a[i4*4+3];
                f1 += z.x * w1b[i4*4+0] + z.y * w1b[i4*4+1]
                    + z.z * w1b[i4*4+2] + z.w * w1b[i4*4+3];
            }
            f_s[warp][ch][lane]      = fmaxf(f0, 0.f);
            f_s[warp][ch][32 + lane] = fmaxf(f1, 0.f);
        }
        __syncwarp();

        // FFN layer 2: out = h1 + f @ W2
        #pragma unroll
        for (int ch = 0; ch < 4; ch++) {
            float acc = g_h1[(gpos * Nz + n0 + ch) * Dz + lane];
            const float4* fp = (const float4*)f_s[warp][ch];
            #pragma unroll
            for (int j4 = 0; j4 < 16; j4++) {
                float4 f = fp[j4];
                acc += f.x * w2[j4*4+0] + f.y * w2[j4*4+1]
                     + f.z * w2[j4*4+2] + f.w * w2[j4*4+3];
            }
            out[(((long)b * Sz + s) * Nz + n0 + ch) * Dz + lane] = acc;
        }
        __syncwarp();
    }
}

// ---------------- launch ------------------------------------------------------
extern "C" void kernel_launch(void* const* d_in, const int* in_sizes, int n_in,
                              void* d_out, int out_size) {
    const float* x        = (const float*)d_in[0];
    const float* ox       = (const float*)d_in[1];
    const float* start_W  = (const float*)d_in[2];
    const float* start_b  = (const float*)d_in[3];
    const float* Wq       = (const float*)d_in[4];
    const float* Wk       = (const float*)d_in[5];
    const float* Wv       = (const float*)d_in[6];
    const float* Wo       = (const float*)d_in[7];
    const float* ln1_g    = (const float*)d_in[8];
    const float* ln1_b    = (const float*)d_in[9];
    const float* ln2_g    = (const float*)d_in[10];
    const float* ln2_b    = (const float*)d_in[11];
    const float* W1       = (const float*)d_in[12];
    const float* b1       = (const float*)d_in[13];
    const float* W2       = (const float*)d_in[14];
    const float* b2       = (const float*)d_in[15];
    float* out = (float*)d_out;

    front_kernel<<<258, 256>>>(x, ox, start_W, start_b, Wq, Wk, Wv, Wo,
                               ln1_g, ln1_b);
    attn_kernel<<<Bz * Ez * Nz, 256>>>();
    tail1_kernel<<<Bz * Ez * 16, 128>>>(start_W, start_b, ln2_g, ln2_b, b2);
    tail23_kernel<<<Bz * Ez * 16, 128>>>(W1, b1, W2, out);
}